// round 16
// baseline (speedup 1.0000x reference)
#include <cuda_runtime.h>
#include <cuda_fp16.h>
#include <cstdint>

// ============================================================================
// ConvolutionFromEdgeSetUpdate:
//   messages = relu([node[src] | node[tgt] | edge] @ W + b)   (E x 64)
//   out      = segment_sum(messages, tgt, 50000)
// E=800000, D=64, U=64, K=192.
//
// R16 = R11 (fp16 single product, 2-stage pipeline, TILE_M=64, 2 CTA/SM)
// with the gather INTERLEAVED into the MMA at source level and made
// BRANCHLESS (clamped tile index): LDG batch 1 -> MMA ksteps 0-5 ->
// convert+STS 1 -> LDG batch 2 -> MMA ksteps 6-11 -> convert+STS 2.
// This removes the per-warp ~2x260cyc LDG->STS scoreboard stall that the
// old `if (nxt < N_TILES)` basic-block boundary prevented ptxas from hiding.
// ============================================================================

#define NN_NODES 50000
#define NN_EDGES 800000
#define D_FEAT   64
#define UNITS    64
#define KDIM     192
#define TILE_M   64
#define N_TILES  (NN_EDGES / TILE_M)   // 12500
#define THREADS  256                   // 8 warps: 4 mg x 2 ng
#define GRID_X   296                   // 2 CTAs per SM

// SMEM: padded rows (200 fp16 = 400B); 400 mod 128 = 16 -> ldsm conflict-free.
#define STRIDE_B   400
#define SM_A0      0
#define SM_A1      (SM_A0 + TILE_M * STRIDE_B)       // 25600
#define SM_B       (SM_A1 + TILE_M * STRIDE_B)       // 51200
#define SM_IDX     (SM_B + UNITS * STRIDE_B)         // 76800: 2 bufs x 128 int
#define SM_TOTAL   (SM_IDX + 2 * 128 * 4)            // 77824 -> 2 CTAs/SM

// ---------------- helpers ----------------

__device__ __forceinline__ uint32_t smem_to_u32(const void* smem_ptr) {
    uint32_t addr;
    asm("{ .reg .u64 tmp; cvta.to.shared.u64 tmp, %1; cvt.u32.u64 %0, tmp; }"
        : "=r"(addr) : "l"(smem_ptr));
    return addr;
}

__device__ __forceinline__ void ldsm_x4(uint32_t* r, uint32_t addr) {
    asm volatile("ldmatrix.sync.aligned.m8n8.x4.shared.b16 {%0,%1,%2,%3}, [%4];"
        : "=r"(r[0]), "=r"(r[1]), "=r"(r[2]), "=r"(r[3]) : "r"(addr));
}

__device__ __forceinline__ void ldsm_x2(uint32_t* r, uint32_t addr) {
    asm volatile("ldmatrix.sync.aligned.m8n8.x2.shared.b16 {%0,%1}, [%2];"
        : "=r"(r[0]), "=r"(r[1]) : "r"(addr));
}

__device__ __forceinline__ void mma_f16(float* c, const uint32_t* a, const uint32_t* b) {
    asm volatile(
        "mma.sync.aligned.m16n8k16.row.col.f32.f16.f16.f32 "
        "{%0,%1,%2,%3}, {%4,%5,%6,%7}, {%8,%9}, {%0,%1,%2,%3};"
        : "+f"(c[0]), "+f"(c[1]), "+f"(c[2]), "+f"(c[3])
        : "r"(a[0]), "r"(a[1]), "r"(a[2]), "r"(a[3]), "r"(b[0]), "r"(b[1]));
}

__device__ __forceinline__ uint32_t pack_h2(float a, float b) {
    __half2 t = __halves2half2(__float2half_rn(a), __float2half_rn(b));
    return *reinterpret_cast<uint32_t*>(&t);
}

// ---------------- zero output (d_out is poisoned 0xAA) ----------------

__global__ void zero_out_kernel(float4* out) {
    int i = blockIdx.x * blockDim.x + threadIdx.x;
    if (i < NN_NODES * UNITS / 4) out[i] = make_float4(0.f, 0.f, 0.f, 0.f);
}

// ---------------- main fused kernel ----------------

__global__ __launch_bounds__(THREADS, 2)
void edgeconv_kernel(const float* __restrict__ node_feat,
                     const float* __restrict__ edge_feat,
                     const int*   __restrict__ src_idx,
                     const int*   __restrict__ tgt_idx,
                     const float* __restrict__ W,
                     const float* __restrict__ bias,
                     float*       __restrict__ out)
{
    extern __shared__ char smem[];
    const uint32_t smem_base = smem_to_u32(smem);
    const int tid  = threadIdx.x;
    const int wid  = tid >> 5;
    const int lane = tid & 31;

    int* const idx_sm = reinterpret_cast<int*>(smem + SM_IDX);

    // ---- build B = W^T (single fp16) in SMEM: Bsm[n][k], k contiguous ----
    for (int task = tid; task < 192; task += THREADS) {
        const int n = task & 63, bseg = task >> 6;
        char* rowp = smem + SM_B + n * STRIDE_B;
        #pragma unroll 8
        for (int j = 0; j < 64; ++j) {
            const int k = bseg * 64 + j;
            *reinterpret_cast<__half*>(rowp + k * 2) = __float2half_rn(W[k * UNITS + n]);
        }
    }

    // warp tile: mg in {0..3} picks 16 rows, ng in {0,1} picks 32 cols
    const int mg = wid >> 1;
    const int ng = wid & 1;
    const int t4 = lane & 3;
    const int g  = lane >> 2;
    const int r0 = mg * 16 + g;           // epilogue row within tile (0..63)

    // per-thread bias: cols ng*32 + j*8 + 2*t4 + {0,1}
    float bj0[4], bj1[4];
    #pragma unroll
    for (int j = 0; j < 4; ++j) {
        bj0[j] = bias[ng * 32 + j * 8 + 2 * t4];
        bj1[j] = bias[ng * 32 + j * 8 + 2 * t4 + 1];
    }

    // ldmatrix per-lane address components (byte offsets)
    const uint32_t a_lane_off =
        (uint32_t)((mg * 16 + (lane & 15)) * STRIDE_B + (lane >> 4) * 16);
    const uint32_t b_lane_off =
        (uint32_t)((ng * 32 + (lane & 7)) * STRIDE_B + ((lane >> 3) & 1) * 16);

    const uint32_t bB = smem_base + SM_B + b_lane_off;

    // coalesced gather mapping: 16 threads per (row,seg), one float4 each
    const int g_chunk = tid & 15;          // float4 index within 64-float row
    const int g_rs0   = tid >> 4;          // first rowseg (0..15), step 16

    // ======== prologue: idx(t0) -> buf0 ========
    const int tile0 = blockIdx.x;
    if (tid < 128) {
        const int e = tile0 * TILE_M + (tid & 63);
        idx_sm[tid] = (tid < 64) ? __ldg(src_idx + e) : __ldg(tgt_idx + e);
    }
    __syncthreads();   // B + idx(t0) ready

    // gather(t0) -> A buf0 (plain two-batch form; prologue is off the clock)
    {
        const int* idxp = idx_sm;
        #pragma unroll
        for (int half = 0; half < 2; ++half) {
            const float* p[6]; int rowv[6], segv[6];
            #pragma unroll
            for (int i = 0; i < 6; ++i) {
                const int rs  = g_rs0 + (half * 6 + i) * 16;
                const int row = rs & (TILE_M - 1);
                const int seg = rs >> 6;
                rowv[i] = row; segv[i] = seg;
                p[i] = (seg == 2)
                     ? edge_feat + (size_t)(tile0 * TILE_M + row) * D_FEAT
                     : node_feat + (size_t)idxp[rs] * D_FEAT;
            }
            float4 v[6];
            #pragma unroll
            for (int i = 0; i < 6; ++i)
                v[i] = __ldg(reinterpret_cast<const float4*>(p[i]) + g_chunk);
            #pragma unroll
            for (int i = 0; i < 6; ++i) {
                uint2 hh;
                hh.x = pack_h2(v[i].x, v[i].y);
                hh.y = pack_h2(v[i].z, v[i].w);
                const uint32_t off =
                    (uint32_t)(rowv[i] * STRIDE_B + segv[i] * 128 + g_chunk * 8);
                *reinterpret_cast<uint2*>(smem + SM_A0 + off) = hh;
            }
        }
    }
    int tgtr0 = idx_sm[64 + r0];
    int tgtr1 = idx_sm[64 + r0 + 8];
    if (tid < 128) {
        const int nt = (tile0 + GRID_X < N_TILES) ? tile0 + GRID_X : tile0;
        const int e = nt * TILE_M + (tid & 63);
        idx_sm[128 + tid] = (tid < 64) ? __ldg(src_idx + e) : __ldg(tgt_idx + e);
    }
    __syncthreads();   // A buf0 + idx(t0+G) ready

    // ======== pipelined main loop: branchless, interleaved ========
    int p = 0, q = 0;
    for (int tile = tile0; tile < N_TILES; tile += GRID_X) {
        // clamp: past-the-end iterations redo the last valid tile's gather
        // into a dead buffer (indices remain valid; result discarded).
        const int nxt = (tile + GRID_X < N_TILES) ? tile + GRID_X : tile;
        const int* idxp = idx_sm + (q ^ 1) * 128;
        const uint32_t abase = (p ^ 1) ? SM_A1 : SM_A0;
        const uint32_t aA = smem_base + (p ? SM_A1 : SM_A0) + a_lane_off;

        float acc[4][4];
        #pragma unroll
        for (int j = 0; j < 4; ++j) {
            acc[j][0] = 0.f; acc[j][1] = 0.f; acc[j][2] = 0.f; acc[j][3] = 0.f;
        }

        // ---- LDG batch 1 (rowsegs 0..5) ----
        float4 v1[6]; int row1[6], seg1[6];
        #pragma unroll
        for (int i = 0; i < 6; ++i) {
            const int rs  = g_rs0 + i * 16;
            const int row = rs & (TILE_M - 1);
            const int seg = rs >> 6;
            row1[i] = row; seg1[i] = seg;
            const float* pp = (seg == 2)
                 ? edge_feat + (size_t)(nxt * TILE_M + row) * D_FEAT
                 : node_feat + (size_t)idxp[rs] * D_FEAT;
            v1[i] = __ldg(reinterpret_cast<const float4*>(pp) + g_chunk);
        }

        // ---- MMA ksteps 0..5 (independent of v1; hides batch-1 latency) ----
        #pragma unroll
        for (int ks = 0; ks < 6; ++ks) {
            const uint32_t kb = (uint32_t)(ks * 32);
            uint32_t aa[4];
            ldsm_x4(aa, aA + kb);
            #pragma unroll
            for (int j = 0; j < 4; ++j) {
                uint32_t bb[2];
                ldsm_x2(bb, bB + (uint32_t)(j * 8 * STRIDE_B) + kb);
                mma_f16(acc[j], aa, bb);
            }
        }

        // ---- convert + STS batch 1 ----
        #pragma unroll
        for (int i = 0; i < 6; ++i) {
            uint2 hh;
            hh.x = pack_h2(v1[i].x, v1[i].y);
            hh.y = pack_h2(v1[i].z, v1[i].w);
            const uint32_t off =
                (uint32_t)(row1[i] * STRIDE_B + seg1[i] * 128 + g_chunk * 8);
            *reinterpret_cast<uint2*>(smem + abase + off) = hh;
        }

        // ---- LDG batch 2 (rowsegs 6..11) ----
        float4 v2[6]; int row2[6], seg2[6];
        #pragma unroll
        for (int i = 0; i < 6; ++i) {
            const int rs  = g_rs0 + (6 + i) * 16;
            const int row = rs & (TILE_M - 1);
            const int seg = rs >> 6;
            row2[i] = row; seg2[i] = seg;
            const float* pp = (seg == 2)
                 ? edge_feat + (size_t)(nxt * TILE_M + row) * D_FEAT
                 : node_feat + (size_t)idxp[rs] * D_FEAT;
            v2[i] = __ldg(reinterpret_cast<const float4*>(pp) + g_chunk);
        }

        // ---- MMA ksteps 6..11 (hides batch-2 latency) ----
        #pragma unroll
        for (int ks = 6; ks < 12; ++ks) {
            const uint32_t kb = (uint32_t)(ks * 32);
            uint32_t aa[4];
            ldsm_x4(aa, aA + kb);
            #pragma unroll
            for (int j = 0; j < 4; ++j) {
                uint32_t bb[2];
                ldsm_x2(bb, bB + (uint32_t)(j * 8 * STRIDE_B) + kb);
                mma_f16(acc[j], aa, bb);
            }
        }

        // ---- convert + STS batch 2 ----
        #pragma unroll
        for (int i = 0; i < 6; ++i) {
            uint2 hh;
            hh.x = pack_h2(v2[i].x, v2[i].y);
            hh.y = pack_h2(v2[i].z, v2[i].w);
            const uint32_t off =
                (uint32_t)(row2[i] * STRIDE_B + seg2[i] * 128 + g_chunk * 8);
            *reinterpret_cast<uint2*>(smem + abase + off) = hh;
        }

        // ---- next-tile bookkeeping (reads of idxp, then restage buf q) ----
        const int ntgt0 = idxp[64 + r0];
        const int ntgt1 = idxp[64 + r0 + 8];
        if (tid < 128) {
            const int nn = (nxt + GRID_X < N_TILES) ? nxt + GRID_X : nxt;
            const int e = nn * TILE_M + (tid & 63);
            idx_sm[q * 128 + tid] =
                (tid < 64) ? __ldg(src_idx + e) : __ldg(tgt_idx + e);
        }

        // ---- epilogue(tile): bias + relu + red.v2 scatter ----
        {
            float* o0 = out + (size_t)tgtr0 * UNITS + ng * 32 + 2 * t4;
            float* o1 = out + (size_t)tgtr1 * UNITS + ng * 32 + 2 * t4;
            #pragma unroll
            for (int j = 0; j < 4; ++j) {
                float w0 = fmaxf(acc[j][0] + bj0[j], 0.f);
                float w1 = fmaxf(acc[j][1] + bj1[j], 0.f);
                float w2 = fmaxf(acc[j][2] + bj0[j], 0.f);
                float w3 = fmaxf(acc[j][3] + bj1[j], 0.f);
                asm volatile("red.global.add.v2.f32 [%0], {%1, %2};"
                             :: "l"(o0 + j * 8), "f"(w0), "f"(w1) : "memory");
                asm volatile("red.global.add.v2.f32 [%0], {%1, %2};"
                             :: "l"(o1 + j * 8), "f"(w2), "f"(w3) : "memory");
            }
        }

        __syncthreads();   // A buf p^1 written, idx buf q staged, buf p free
        tgtr0 = ntgt0; tgtr1 = ntgt1;
        p ^= 1; q ^= 1;
    }
}

// ---------------- launch ----------------

extern "C" void kernel_launch(void* const* d_in, const int* in_sizes, int n_in,
                              void* d_out, int out_size) {
    const float* node_feat = (const float*)d_in[0];
    const float* edge_feat = (const float*)d_in[1];
    const int*   src_idx   = (const int*)d_in[2];
    const int*   tgt_idx   = (const int*)d_in[3];
    const float* W         = (const float*)d_in[4];
    const float* b         = (const float*)d_in[5];
    float* out = (float*)d_out;

    int n4 = NN_NODES * UNITS / 4;
    zero_out_kernel<<<(n4 + 255) / 256, 256>>>((float4*)out);

    static int configured = 0;
    if (!configured) {
        cudaFuncSetAttribute(edgeconv_kernel,
                             cudaFuncAttributeMaxDynamicSharedMemorySize, SM_TOTAL);
        configured = 1;
    }
    edgeconv_kernel<<<GRID_X, THREADS, SM_TOTAL>>>(
        node_feat, edge_feat, src_idx, tgt_idx, W, b, out);
}